// round 5
// baseline (speedup 1.0000x reference)
#include <cuda_runtime.h>

#define CB 4
#define CS 2048
#define CD 1024
#define CH 16
#define CDK 64
#define MTOK (CB*CS)          /* 8192 token rows */

/* GEMM shape: all four projections are [8192,1024] @ [1024,1024] */
#define GM MTOK
#define GN CD
#define GK CD

/* scratch (device globals: allocation-free, graph-capturable) */
__device__ float g_q[MTOK * CD];
__device__ float g_k[MTOK * CD];
__device__ float g_v[MTOK * CD];
__device__ float g_ctx[MTOK * CD];

/* ------------------------------------------------------------------ */
/* SGEMM with bias: C[M,N] = A[M,K] @ W[K,N] + bias                   */
/* 128x128 tile, BK=16, 256 threads, 8x8 per thread (split-tile +-64) */
/* ------------------------------------------------------------------ */
__global__ __launch_bounds__(256, 2)
void gemm_bias_kernel(const float* __restrict__ A, const float* __restrict__ W,
                      const float* __restrict__ bias, float* __restrict__ C)
{
    __shared__ float As[16][132];   /* transposed: As[k][m], padded */
    __shared__ float Bs[16][132];   /* Bs[k][n], padded             */

    const int tid = threadIdx.x;
    const int tx = tid & 15;
    const int ty = tid >> 4;
    const int bm = blockIdx.y * 128;
    const int bn = blockIdx.x * 128;

    float acc[8][8];
#pragma unroll
    for (int i = 0; i < 8; i++)
#pragma unroll
        for (int j = 0; j < 8; j++) acc[i][j] = 0.f;

    const int ar = tid >> 2;          /* 0..63 (+64)  */
    const int ac = (tid & 3) << 2;    /* 0,4,8,12     */
    const int br = tid >> 5;          /* 0..7  (+8)   */
    const int bc = (tid & 31) << 2;   /* 0..124       */

    for (int k0 = 0; k0 < GK; k0 += 16) {
#pragma unroll
        for (int hh = 0; hh < 2; hh++) {
            int r = ar + hh * 64;
            float4 f = *(const float4*)(A + (size_t)(bm + r) * GK + k0 + ac);
            As[ac + 0][r] = f.x; As[ac + 1][r] = f.y;
            As[ac + 2][r] = f.z; As[ac + 3][r] = f.w;
        }
#pragma unroll
        for (int hh = 0; hh < 2; hh++) {
            int r = br + hh * 8;
            *(float4*)&Bs[r][bc] =
                *(const float4*)(W + (size_t)(k0 + r) * GN + bn + bc);
        }
        __syncthreads();

#pragma unroll
        for (int kk = 0; kk < 16; kk++) {
            float a[8], b[8];
            *(float4*)&a[0] = *(const float4*)&As[kk][ty * 4];
            *(float4*)&a[4] = *(const float4*)&As[kk][ty * 4 + 64];
            *(float4*)&b[0] = *(const float4*)&Bs[kk][tx * 4];
            *(float4*)&b[4] = *(const float4*)&Bs[kk][tx * 4 + 64];
#pragma unroll
            for (int i = 0; i < 8; i++)
#pragma unroll
                for (int j = 0; j < 8; j++)
                    acc[i][j] = fmaf(a[i], b[j], acc[i][j]);
        }
        __syncthreads();
    }

    float4 bia0 = *(const float4*)(bias + bn + tx * 4);
    float4 bia1 = *(const float4*)(bias + bn + tx * 4 + 64);
#pragma unroll
    for (int i = 0; i < 8; i++) {
        int row = bm + ((i < 4) ? (ty * 4 + i) : (64 + ty * 4 + i - 4));
        float4 r0, r1;
        r0.x = acc[i][0] + bia0.x; r0.y = acc[i][1] + bia0.y;
        r0.z = acc[i][2] + bia0.z; r0.w = acc[i][3] + bia0.w;
        r1.x = acc[i][4] + bia1.x; r1.y = acc[i][5] + bia1.y;
        r1.z = acc[i][6] + bia1.z; r1.w = acc[i][7] + bia1.w;
        *(float4*)(C + (size_t)row * GN + bn + tx * 4) = r0;
        *(float4*)(C + (size_t)row * GN + bn + tx * 4 + 64) = r1;
    }
}

/* ------------------------------------------------------------------ */
/* Flash attention (causal), 64x64 tiles, DK=64, online softmax.      */
/* One CTA per (q-tile, b, h). Masked k-tiles are skipped entirely.   */
/* ------------------------------------------------------------------ */
#define FST 68   /* smem row stride (floats) */

__global__ __launch_bounds__(256)
void flash_kernel(const float* __restrict__ q, const float* __restrict__ k,
                  const float* __restrict__ v, float* __restrict__ ctx)
{
    extern __shared__ float sm[];
    float* Qs  = sm;                 /* [64][FST]  transposed: Qs[d][i] */
    float* Ks  = sm + 64 * FST;      /* [64][FST]  transposed: Ks[d][j] */
    float* Vs  = sm + 2 * 64 * FST;  /* [64][FST]  row-major:  Vs[j][d] */
    float* Ps  = sm + 3 * 64 * FST;  /* [64][FST]  scores / probs       */
    float* m_s = sm + 4 * 64 * FST;  /* [64] row max                    */
    float* l_s = m_s + 64;           /* [64] row sum                    */
    float* rs_s = l_s + 64;          /* [64] rescale factor             */

    const int tid = threadIdx.x;
    const int tx = tid & 15;
    const int ty = tid >> 4;
    const int i0 = ty * 4;           /* q-row block      */
    const int d0 = tx * 4;           /* col block (j or d) */
    const int qt = blockIdx.x;       /* 0..31 q tile     */
    const int bh = blockIdx.y;       /* 0..63            */
    const int b  = bh >> 4;
    const int h  = bh & 15;
    const int qbase = qt * 64;

    const float* qp = q + ((size_t)b * CS + qbase) * CD + h * CDK;
    const float* kp = k + ((size_t)b * CS) * CD + h * CDK;
    const float* vp = v + ((size_t)b * CS) * CD + h * CDK;

    /* load Q tile (transposed into smem) */
    {
        int i  = tid >> 2;
        int c0 = (tid & 3) << 4;
        const float* src = qp + (size_t)i * CD + c0;
#pragma unroll
        for (int r = 0; r < 4; r++) {
            float4 f = *(const float4*)(src + r * 4);
            int d = c0 + r * 4;
            Qs[(d + 0) * FST + i] = f.x; Qs[(d + 1) * FST + i] = f.y;
            Qs[(d + 2) * FST + i] = f.z; Qs[(d + 3) * FST + i] = f.w;
        }
    }
    if (tid < 64) { m_s[tid] = -1e30f; l_s[tid] = 0.f; }

    float o[4][4];
#pragma unroll
    for (int i = 0; i < 4; i++)
#pragma unroll
        for (int j = 0; j < 4; j++) o[i][j] = 0.f;

    for (int kt = 0; kt <= qt; kt++) {
        __syncthreads();   /* protect smem reuse + first-iter Q/m/l init */

        /* load K (transposed) and V tiles */
        {
            int j  = tid >> 2;
            int c0 = (tid & 3) << 4;
            const float* ksrc = kp + (size_t)(kt * 64 + j) * CD + c0;
#pragma unroll
            for (int r = 0; r < 4; r++) {
                float4 f = *(const float4*)(ksrc + r * 4);
                int d = c0 + r * 4;
                Ks[(d + 0) * FST + j] = f.x; Ks[(d + 1) * FST + j] = f.y;
                Ks[(d + 2) * FST + j] = f.z; Ks[(d + 3) * FST + j] = f.w;
            }
            const float* vsrc = vp + (size_t)(kt * 64 + j) * CD + c0;
#pragma unroll
            for (int r = 0; r < 4; r++)
                *(float4*)(Vs + j * FST + c0 + r * 4) =
                    *(const float4*)(vsrc + r * 4);
        }
        __syncthreads();

        /* S = Q @ K^T (each thread 4x4) */
        float s[4][4];
#pragma unroll
        for (int i = 0; i < 4; i++)
#pragma unroll
            for (int j = 0; j < 4; j++) s[i][j] = 0.f;
#pragma unroll 16
        for (int d = 0; d < 64; d++) {
            float4 qf = *(const float4*)(Qs + d * FST + i0);
            float4 kf = *(const float4*)(Ks + d * FST + d0);
            s[0][0] = fmaf(qf.x, kf.x, s[0][0]); s[0][1] = fmaf(qf.x, kf.y, s[0][1]);
            s[0][2] = fmaf(qf.x, kf.z, s[0][2]); s[0][3] = fmaf(qf.x, kf.w, s[0][3]);
            s[1][0] = fmaf(qf.y, kf.x, s[1][0]); s[1][1] = fmaf(qf.y, kf.y, s[1][1]);
            s[1][2] = fmaf(qf.y, kf.z, s[1][2]); s[1][3] = fmaf(qf.y, kf.w, s[1][3]);
            s[2][0] = fmaf(qf.z, kf.x, s[2][0]); s[2][1] = fmaf(qf.z, kf.y, s[2][1]);
            s[2][2] = fmaf(qf.z, kf.z, s[2][2]); s[2][3] = fmaf(qf.z, kf.w, s[2][3]);
            s[3][0] = fmaf(qf.w, kf.x, s[3][0]); s[3][1] = fmaf(qf.w, kf.y, s[3][1]);
            s[3][2] = fmaf(qf.w, kf.z, s[3][2]); s[3][3] = fmaf(qf.w, kf.w, s[3][3]);
        }

        const bool diag = (kt == qt);
#pragma unroll
        for (int ii = 0; ii < 4; ii++)
#pragma unroll
            for (int jj = 0; jj < 4; jj++) {
                float val = s[ii][jj] * 0.125f;   /* 1/sqrt(64) */
                if (diag && (d0 + jj > i0 + ii)) val = -1e30f;
                Ps[(i0 + ii) * FST + d0 + jj] = val;
            }
        __syncthreads();

        /* online softmax stats: 4 threads per row */
        {
            int r = tid >> 2;
            int p = tid & 3;
            float* row = Ps + r * FST + p * 16;
            float mx = -1e30f;
#pragma unroll
            for (int c = 0; c < 16; c++) mx = fmaxf(mx, row[c]);
            mx = fmaxf(mx, __shfl_xor_sync(0xffffffffu, mx, 1));
            mx = fmaxf(mx, __shfl_xor_sync(0xffffffffu, mx, 2));
            float mprev = m_s[r];
            float mnew  = fmaxf(mprev, mx);
            float lsum = 0.f;
#pragma unroll
            for (int c = 0; c < 16; c++) {
                float e = __expf(row[c] - mnew);
                row[c] = e;
                lsum += e;
            }
            lsum += __shfl_xor_sync(0xffffffffu, lsum, 1);
            lsum += __shfl_xor_sync(0xffffffffu, lsum, 2);
            if (p == 0) {
                float rf = __expf(mprev - mnew);
                rs_s[r] = rf;
                l_s[r]  = l_s[r] * rf + lsum;
                m_s[r]  = mnew;
            }
        }
        __syncthreads();

        /* rescale accumulator, then O += P @ V */
        {
            float rf0 = rs_s[i0 + 0], rf1 = rs_s[i0 + 1];
            float rf2 = rs_s[i0 + 2], rf3 = rs_s[i0 + 3];
#pragma unroll
            for (int jj = 0; jj < 4; jj++) {
                o[0][jj] *= rf0; o[1][jj] *= rf1;
                o[2][jj] *= rf2; o[3][jj] *= rf3;
            }
        }
#pragma unroll 8
        for (int j = 0; j < 64; j++) {
            float4 vf = *(const float4*)(Vs + j * FST + d0);
            float p0 = Ps[(i0 + 0) * FST + j];
            float p1 = Ps[(i0 + 1) * FST + j];
            float p2 = Ps[(i0 + 2) * FST + j];
            float p3 = Ps[(i0 + 3) * FST + j];
            o[0][0] = fmaf(p0, vf.x, o[0][0]); o[0][1] = fmaf(p0, vf.y, o[0][1]);
            o[0][2] = fmaf(p0, vf.z, o[0][2]); o[0][3] = fmaf(p0, vf.w, o[0][3]);
            o[1][0] = fmaf(p1, vf.x, o[1][0]); o[1][1] = fmaf(p1, vf.y, o[1][1]);
            o[1][2] = fmaf(p1, vf.z, o[1][2]); o[1][3] = fmaf(p1, vf.w, o[1][3]);
            o[2][0] = fmaf(p2, vf.x, o[2][0]); o[2][1] = fmaf(p2, vf.y, o[2][1]);
            o[2][2] = fmaf(p2, vf.z, o[2][2]); o[2][3] = fmaf(p2, vf.w, o[2][3]);
            o[3][0] = fmaf(p3, vf.x, o[3][0]); o[3][1] = fmaf(p3, vf.y, o[3][1]);
            o[3][2] = fmaf(p3, vf.z, o[3][2]); o[3][3] = fmaf(p3, vf.w, o[3][3]);
        }
    }

    /* epilogue: normalize and write ctx */
    float* op = ctx + ((size_t)b * CS + qbase) * CD + h * CDK;
#pragma unroll
    for (int ii = 0; ii < 4; ii++) {
        float inv = 1.f / l_s[i0 + ii];
        float4 f;
        f.x = o[ii][0] * inv; f.y = o[ii][1] * inv;
        f.z = o[ii][2] * inv; f.w = o[ii][3] * inv;
        *(float4*)(op + (size_t)(i0 + ii) * CD + d0) = f;
    }
}

/* ------------------------------------------------------------------ */
extern "C" void kernel_launch(void* const* d_in, const int* in_sizes, int n_in,
                              void* d_out, int out_size)
{
    const float* Q  = (const float*)d_in[0];
    const float* KV = (const float*)d_in[1];
    /* d_in[2] = mask (bool causal) — applied analytically in flash_kernel */
    const float* Wq = (const float*)d_in[3];
    const float* bq = (const float*)d_in[4];
    const float* Wk = (const float*)d_in[5];
    const float* bk = (const float*)d_in[6];
    const float* Wv = (const float*)d_in[7];
    const float* bv = (const float*)d_in[8];
    const float* Wo = (const float*)d_in[9];
    const float* bo = (const float*)d_in[10];
    float* out = (float*)d_out;

    float *pq, *pk, *pv, *pctx;
    cudaGetSymbolAddress((void**)&pq,   g_q);
    cudaGetSymbolAddress((void**)&pk,   g_k);
    cudaGetSymbolAddress((void**)&pv,   g_v);
    cudaGetSymbolAddress((void**)&pctx, g_ctx);

    dim3 gg(GN / 128, GM / 128);   /* (8, 64) */

    gemm_bias_kernel<<<gg, 256>>>(Q,  Wq, bq, pq);
    gemm_bias_kernel<<<gg, 256>>>(KV, Wk, bk, pk);
    gemm_bias_kernel<<<gg, 256>>>(KV, Wv, bv, pv);

    const int smem = (4 * 64 * FST + 3 * 64) * (int)sizeof(float);  /* ~70.4 KB */
    cudaFuncSetAttribute(flash_kernel,
                         cudaFuncAttributeMaxDynamicSharedMemorySize, smem);
    dim3 gf(CS / 64, CB * CH);     /* (32, 64) */
    flash_kernel<<<gf, 256, smem>>>(pq, pk, pv, pctx);

    gemm_bias_kernel<<<gg, 256>>>(pctx, Wo, bo, out);
}

// round 7
// speedup vs baseline: 1.5191x; 1.5191x over previous
#include <cuda_runtime.h>

#define CB 4
#define CS 2048
#define CD 1024
#define CH 16
#define CDK 64
#define MTOK (CB*CS)          /* 8192 token rows */

#define GM MTOK
#define GN CD
#define GK CD

/* scratch (device globals: allocation-free, graph-capturable) */
__device__ float g_q[MTOK * CD];
__device__ float g_k[MTOK * CD];
__device__ float g_v[MTOK * CD];
__device__ float g_ctx[MTOK * CD];

/* ------------------------------------------------------------------ */
/* tf32 tensor-core GEMM: C[M,N] = A[M,K] @ W[K,N] + bias             */
/* 128x128x16 tile, 8 warps (warp tile 32x64), mma.m16n8k8 tf32,      */
/* double-buffered smem, conflict-free fragment strides.              */
/* ------------------------------------------------------------------ */
#define AST 20    /* A smem row stride (floats): (20r+c)%32 distinct  */
#define BST 136   /* B smem row stride (floats): (8k+n)%32 distinct   */

__device__ __forceinline__ unsigned f2tf(float f) {
    unsigned u;
    asm("cvt.rna.tf32.f32 %0, %1;" : "=r"(u) : "f"(f));
    return u;
}

__device__ __forceinline__ void mma_tf32(float* c, const unsigned* a, const unsigned* b) {
    asm volatile(
        "mma.sync.aligned.m16n8k8.row.col.f32.tf32.tf32.f32 "
        "{%0,%1,%2,%3}, {%4,%5,%6,%7}, {%8,%9}, {%0,%1,%2,%3};"
        : "+f"(c[0]), "+f"(c[1]), "+f"(c[2]), "+f"(c[3])
        : "r"(a[0]), "r"(a[1]), "r"(a[2]), "r"(a[3]), "r"(b[0]), "r"(b[1]));
}

__global__ __launch_bounds__(256, 2)
void gemm_tf32_kernel(const float* __restrict__ A, const float* __restrict__ W,
                      const float* __restrict__ bias, float* __restrict__ C)
{
    __shared__ float As[2][128 * AST];
    __shared__ float Bs[2][16 * BST];

    const int tid  = threadIdx.x;
    const int lane = tid & 31;
    const int gr   = lane >> 2;     /* group row 0..7   */
    const int tg   = lane & 3;      /* thread-in-group  */
    const int warp = tid >> 5;
    const int wm   = (warp & 3) * 32;
    const int wn   = (warp >> 2) * 64;
    const int bm   = blockIdx.y * 128;
    const int bn   = blockIdx.x * 128;

    /* global->smem copy indices */
    const int ar = tid >> 2;          /* 0..63 (+64) A row   */
    const int ac = (tid & 3) * 4;     /* A col 0,4,8,12      */
    const int br = tid >> 5;          /* 0..7 (+8) B row     */
    const int bc = (tid & 31) * 4;    /* B col               */

    float acc[2][8][4];
#pragma unroll
    for (int mt = 0; mt < 2; mt++)
#pragma unroll
        for (int nt = 0; nt < 8; nt++)
#pragma unroll
            for (int i = 0; i < 4; i++) acc[mt][nt][i] = 0.f;

    const float* Ab = A + (size_t)bm * GK;

    /* prefetch tile 0 */
    float4 pa0 = *(const float4*)(Ab + (size_t)ar * GK + ac);
    float4 pa1 = *(const float4*)(Ab + (size_t)(ar + 64) * GK + ac);
    float4 pb0 = *(const float4*)(W + (size_t)br * GN + bn + bc);
    float4 pb1 = *(const float4*)(W + (size_t)(br + 8) * GN + bn + bc);

    /* store tile 0 into buf 0 (cvt to tf32 bits) */
    {
        float* as = As[0];
        as[ar * AST + ac + 0] = __uint_as_float(f2tf(pa0.x));
        as[ar * AST + ac + 1] = __uint_as_float(f2tf(pa0.y));
        as[ar * AST + ac + 2] = __uint_as_float(f2tf(pa0.z));
        as[ar * AST + ac + 3] = __uint_as_float(f2tf(pa0.w));
        as[(ar + 64) * AST + ac + 0] = __uint_as_float(f2tf(pa1.x));
        as[(ar + 64) * AST + ac + 1] = __uint_as_float(f2tf(pa1.y));
        as[(ar + 64) * AST + ac + 2] = __uint_as_float(f2tf(pa1.z));
        as[(ar + 64) * AST + ac + 3] = __uint_as_float(f2tf(pa1.w));
        float* bs = Bs[0];
        bs[br * BST + bc + 0] = __uint_as_float(f2tf(pb0.x));
        bs[br * BST + bc + 1] = __uint_as_float(f2tf(pb0.y));
        bs[br * BST + bc + 2] = __uint_as_float(f2tf(pb0.z));
        bs[br * BST + bc + 3] = __uint_as_float(f2tf(pb0.w));
        bs[(br + 8) * BST + bc + 0] = __uint_as_float(f2tf(pb1.x));
        bs[(br + 8) * BST + bc + 1] = __uint_as_float(f2tf(pb1.y));
        bs[(br + 8) * BST + bc + 2] = __uint_as_float(f2tf(pb1.z));
        bs[(br + 8) * BST + bc + 3] = __uint_as_float(f2tf(pb1.w));
    }
    __syncthreads();

    int buf = 0;
    for (int kt = 0; kt < GK / 16; kt++) {
        /* prefetch next tile from global */
        if (kt < GK / 16 - 1) {
            const float* Ap = Ab + (kt + 1) * 16;
            pa0 = *(const float4*)(Ap + (size_t)ar * GK + ac);
            pa1 = *(const float4*)(Ap + (size_t)(ar + 64) * GK + ac);
            const float* Wp = W + (size_t)(kt + 1) * 16 * GN;
            pb0 = *(const float4*)(Wp + (size_t)br * GN + bn + bc);
            pb1 = *(const float4*)(Wp + (size_t)(br + 8) * GN + bn + bc);
        }

        const float* as = As[buf];
        const float* bs = Bs[buf];
#pragma unroll
        for (int ks = 0; ks < 16; ks += 8) {
            unsigned af[2][4], bf[8][2];
#pragma unroll
            for (int mt = 0; mt < 2; mt++) {
                int r = wm + mt * 16 + gr;
                af[mt][0] = __float_as_uint(as[r * AST + ks + tg]);
                af[mt][1] = __float_as_uint(as[(r + 8) * AST + ks + tg]);
                af[mt][2] = __float_as_uint(as[r * AST + ks + tg + 4]);
                af[mt][3] = __float_as_uint(as[(r + 8) * AST + ks + tg + 4]);
            }
#pragma unroll
            for (int nt = 0; nt < 8; nt++) {
                int c = wn + nt * 8 + gr;
                bf[nt][0] = __float_as_uint(bs[(ks + tg) * BST + c]);
                bf[nt][1] = __float_as_uint(bs[(ks + tg + 4) * BST + c]);
            }
#pragma unroll
            for (int mt = 0; mt < 2; mt++)
#pragma unroll
                for (int nt = 0; nt < 8; nt++)
                    mma_tf32(acc[mt][nt], af[mt], bf[nt]);
        }

        /* store prefetched tile into the other buffer */
        if (kt < GK / 16 - 1) {
            int nb = buf ^ 1;
            float* asw = As[nb];
            asw[ar * AST + ac + 0] = __uint_as_float(f2tf(pa0.x));
            asw[ar * AST + ac + 1] = __uint_as_float(f2tf(pa0.y));
            asw[ar * AST + ac + 2] = __uint_as_float(f2tf(pa0.z));
            asw[ar * AST + ac + 3] = __uint_as_float(f2tf(pa0.w));
            asw[(ar + 64) * AST + ac + 0] = __uint_as_float(f2tf(pa1.x));
            asw[(ar + 64) * AST + ac + 1] = __uint_as_float(f2tf(pa1.y));
            asw[(ar + 64) * AST + ac + 2] = __uint_as_float(f2tf(pa1.z));
            asw[(ar + 64) * AST + ac + 3] = __uint_as_float(f2tf(pa1.w));
            float* bsw = Bs[nb];
            bsw[br * BST + bc + 0] = __uint_as_float(f2tf(pb0.x));
            bsw[br * BST + bc + 1] = __uint_as_float(f2tf(pb0.y));
            bsw[br * BST + bc + 2] = __uint_as_float(f2tf(pb0.z));
            bsw[br * BST + bc + 3] = __uint_as_float(f2tf(pb0.w));
            bsw[(br + 8) * BST + bc + 0] = __uint_as_float(f2tf(pb1.x));
            bsw[(br + 8) * BST + bc + 1] = __uint_as_float(f2tf(pb1.y));
            bsw[(br + 8) * BST + bc + 2] = __uint_as_float(f2tf(pb1.z));
            bsw[(br + 8) * BST + bc + 3] = __uint_as_float(f2tf(pb1.w));
        }
        __syncthreads();
        buf ^= 1;
    }

    /* epilogue: bias + store */
#pragma unroll
    for (int mt = 0; mt < 2; mt++) {
#pragma unroll
        for (int nt = 0; nt < 8; nt++) {
            int row = bm + wm + mt * 16 + gr;
            int col = bn + wn + nt * 8 + tg * 2;
            float2 bb = *(const float2*)(bias + col);
            float2 v0, v1;
            v0.x = acc[mt][nt][0] + bb.x; v0.y = acc[mt][nt][1] + bb.y;
            v1.x = acc[mt][nt][2] + bb.x; v1.y = acc[mt][nt][3] + bb.y;
            *(float2*)(C + (size_t)row * GN + col) = v0;
            *(float2*)(C + (size_t)(row + 8) * GN + col) = v1;
        }
    }
}

/* ------------------------------------------------------------------ */
/* Flash attention (causal), 64x64 tiles, DK=64, online softmax.      */
/* One CTA per (q-tile, b, h). Masked k-tiles are skipped entirely.   */
/* ------------------------------------------------------------------ */
#define FST 68   /* smem row stride (floats) */

__global__ __launch_bounds__(256)
void flash_kernel(const float* __restrict__ q, const float* __restrict__ k,
                  const float* __restrict__ v, float* __restrict__ ctx)
{
    extern __shared__ float sm[];
    float* Qs  = sm;                 /* [64][FST]  transposed: Qs[d][i] */
    float* Ks  = sm + 64 * FST;      /* [64][FST]  transposed: Ks[d][j] */
    float* Vs  = sm + 2 * 64 * FST;  /* [64][FST]  row-major:  Vs[j][d] */
    float* Ps  = sm + 3 * 64 * FST;  /* [64][FST]  scores / probs       */
    float* m_s = sm + 4 * 64 * FST;  /* [64] row max                    */
    float* l_s = m_s + 64;           /* [64] row sum                    */
    float* rs_s = l_s + 64;          /* [64] rescale factor             */

    const int tid = threadIdx.x;
    const int tx = tid & 15;
    const int ty = tid >> 4;
    const int i0 = ty * 4;
    const int d0 = tx * 4;
    const int qt = blockIdx.x;
    const int bh = blockIdx.y;
    const int b  = bh >> 4;
    const int h  = bh & 15;
    const int qbase = qt * 64;

    const float* qp = q + ((size_t)b * CS + qbase) * CD + h * CDK;
    const float* kp = k + ((size_t)b * CS) * CD + h * CDK;
    const float* vp = v + ((size_t)b * CS) * CD + h * CDK;

    {
        int i  = tid >> 2;
        int c0 = (tid & 3) << 4;
        const float* src = qp + (size_t)i * CD + c0;
#pragma unroll
        for (int r = 0; r < 4; r++) {
            float4 f = *(const float4*)(src + r * 4);
            int d = c0 + r * 4;
            Qs[(d + 0) * FST + i] = f.x; Qs[(d + 1) * FST + i] = f.y;
            Qs[(d + 2) * FST + i] = f.z; Qs[(d + 3) * FST + i] = f.w;
        }
    }
    if (tid < 64) { m_s[tid] = -1e30f; l_s[tid] = 0.f; }

    float o[4][4];
#pragma unroll
    for (int i = 0; i < 4; i++)
#pragma unroll
        for (int j = 0; j < 4; j++) o[i][j] = 0.f;

    for (int kt = 0; kt <= qt; kt++) {
        __syncthreads();

        {
            int j  = tid >> 2;
            int c0 = (tid & 3) << 4;
            const float* ksrc = kp + (size_t)(kt * 64 + j) * CD + c0;
#pragma unroll
            for (int r = 0; r < 4; r++) {
                float4 f = *(const float4*)(ksrc + r * 4);
                int d = c0 + r * 4;
                Ks[(d + 0) * FST + j] = f.x; Ks[(d + 1) * FST + j] = f.y;
                Ks[(d + 2) * FST + j] = f.z; Ks[(d + 3) * FST + j] = f.w;
            }
            const float* vsrc = vp + (size_t)(kt * 64 + j) * CD + c0;
#pragma unroll
            for (int r = 0; r < 4; r++)
                *(float4*)(Vs + j * FST + c0 + r * 4) =
                    *(const float4*)(vsrc + r * 4);
        }
        __syncthreads();

        float s[4][4];
#pragma unroll
        for (int i = 0; i < 4; i++)
#pragma unroll
            for (int j = 0; j < 4; j++) s[i][j] = 0.f;
#pragma unroll 16
        for (int d = 0; d < 64; d++) {
            float4 qf = *(const float4*)(Qs + d * FST + i0);
            float4 kf = *(const float4*)(Ks + d * FST + d0);
            s[0][0] = fmaf(qf.x, kf.x, s[0][0]); s[0][1] = fmaf(qf.x, kf.y, s[0][1]);
            s[0][2] = fmaf(qf.x, kf.z, s[0][2]); s[0][3] = fmaf(qf.x, kf.w, s[0][3]);
            s[1][0] = fmaf(qf.y, kf.x, s[1][0]); s[1][1] = fmaf(qf.y, kf.y, s[1][1]);
            s[1][2] = fmaf(qf.y, kf.z, s[1][2]); s[1][3] = fmaf(qf.y, kf.w, s[1][3]);
            s[2][0] = fmaf(qf.z, kf.x, s[2][0]); s[2][1] = fmaf(qf.z, kf.y, s[2][1]);
            s[2][2] = fmaf(qf.z, kf.z, s[2][2]); s[2][3] = fmaf(qf.z, kf.w, s[2][3]);
            s[3][0] = fmaf(qf.w, kf.x, s[3][0]); s[3][1] = fmaf(qf.w, kf.y, s[3][1]);
            s[3][2] = fmaf(qf.w, kf.z, s[3][2]); s[3][3] = fmaf(qf.w, kf.w, s[3][3]);
        }

        const bool diag = (kt == qt);
#pragma unroll
        for (int ii = 0; ii < 4; ii++)
#pragma unroll
            for (int jj = 0; jj < 4; jj++) {
                float val = s[ii][jj] * 0.125f;
                if (diag && (d0 + jj > i0 + ii)) val = -1e30f;
                Ps[(i0 + ii) * FST + d0 + jj] = val;
            }
        __syncthreads();

        {
            int r = tid >> 2;
            int p = tid & 3;
            float* row = Ps + r * FST + p * 16;
            float mx = -1e30f;
#pragma unroll
            for (int c = 0; c < 16; c++) mx = fmaxf(mx, row[c]);
            mx = fmaxf(mx, __shfl_xor_sync(0xffffffffu, mx, 1));
            mx = fmaxf(mx, __shfl_xor_sync(0xffffffffu, mx, 2));
            float mprev = m_s[r];
            float mnew  = fmaxf(mprev, mx);
            float lsum = 0.f;
#pragma unroll
            for (int c = 0; c < 16; c++) {
                float e = __expf(row[c] - mnew);
                row[c] = e;
                lsum += e;
            }
            lsum += __shfl_xor_sync(0xffffffffu, lsum, 1);
            lsum += __shfl_xor_sync(0xffffffffu, lsum, 2);
            if (p == 0) {
                float rf = __expf(mprev - mnew);
                rs_s[r] = rf;
                l_s[r]  = l_s[r] * rf + lsum;
                m_s[r]  = mnew;
            }
        }
        __syncthreads();

        {
            float rf0 = rs_s[i0 + 0], rf1 = rs_s[i0 + 1];
            float rf2 = rs_s[i0 + 2], rf3 = rs_s[i0 + 3];
#pragma unroll
            for (int jj = 0; jj < 4; jj++) {
                o[0][jj] *= rf0; o[1][jj] *= rf1;
                o[2][jj] *= rf2; o[3][jj] *= rf3;
            }
        }
#pragma unroll 8
        for (int j = 0; j < 64; j++) {
            float4 vf = *(const float4*)(Vs + j * FST + d0);
            float p0 = Ps[(i0 + 0) * FST + j];
            float p1 = Ps[(i0 + 1) * FST + j];
            float p2 = Ps[(i0 + 2) * FST + j];
            float p3 = Ps[(i0 + 3) * FST + j];
            o[0][0] = fmaf(p0, vf.x, o[0][0]); o[0][1] = fmaf(p0, vf.y, o[0][1]);
            o[0][2] = fmaf(p0, vf.z, o[0][2]); o[0][3] = fmaf(p0, vf.w, o[0][3]);
            o[1][0] = fmaf(p1, vf.x, o[1][0]); o[1][1] = fmaf(p1, vf.y, o[1][1]);
            o[1][2] = fmaf(p1, vf.z, o[1][2]); o[1][3] = fmaf(p1, vf.w, o[1][3]);
            o[2][0] = fmaf(p2, vf.x, o[2][0]); o[2][1] = fmaf(p2, vf.y, o[2][1]);
            o[2][2] = fmaf(p2, vf.z, o[2][2]); o[2][3] = fmaf(p2, vf.w, o[2][3]);
            o[3][0] = fmaf(p3, vf.x, o[3][0]); o[3][1] = fmaf(p3, vf.y, o[3][1]);
            o[3][2] = fmaf(p3, vf.z, o[3][2]); o[3][3] = fmaf(p3, vf.w, o[3][3]);
        }
    }

    float* op = ctx + ((size_t)b * CS + qbase) * CD + h * CDK;
#pragma unroll
    for (int ii = 0; ii < 4; ii++) {
        float inv = 1.f / l_s[i0 + ii];
        float4 f;
        f.x = o[ii][0] * inv; f.y = o[ii][1] * inv;
        f.z = o[ii][2] * inv; f.w = o[ii][3] * inv;
        *(float4*)(op + (size_t)(i0 + ii) * CD + d0) = f;
    }
}

/* ------------------------------------------------------------------ */
extern "C" void kernel_launch(void* const* d_in, const int* in_sizes, int n_in,
                              void* d_out, int out_size)
{
    const float* Q  = (const float*)d_in[0];
    const float* KV = (const float*)d_in[1];
    /* d_in[2] = mask (bool causal) — applied analytically in flash_kernel */
    const float* Wq = (const float*)d_in[3];
    const float* bq = (const float*)d_in[4];
    const float* Wk = (const float*)d_in[5];
    const float* bk = (const float*)d_in[6];
    const float* Wv = (const float*)d_in[7];
    const float* bv = (const float*)d_in[8];
    const float* Wo = (const float*)d_in[9];
    const float* bo = (const float*)d_in[10];
    float* out = (float*)d_out;

    float *pq, *pk, *pv, *pctx;
    cudaGetSymbolAddress((void**)&pq,   g_q);
    cudaGetSymbolAddress((void**)&pk,   g_k);
    cudaGetSymbolAddress((void**)&pv,   g_v);
    cudaGetSymbolAddress((void**)&pctx, g_ctx);

    dim3 gg(GN / 128, GM / 128);   /* (8, 64) */

    gemm_tf32_kernel<<<gg, 256>>>(Q,  Wq, bq, pq);
    gemm_tf32_kernel<<<gg, 256>>>(KV, Wk, bk, pk);
    gemm_tf32_kernel<<<gg, 256>>>(KV, Wv, bv, pv);

    const int smem = (4 * 64 * FST + 3 * 64) * (int)sizeof(float);  /* ~70.4 KB */
    cudaFuncSetAttribute(flash_kernel,
                         cudaFuncAttributeMaxDynamicSharedMemorySize, smem);
    dim3 gf(CS / 64, CB * CH);     /* (32, 64) */
    flash_kernel<<<gf, 256, smem>>>(pq, pk, pv, pctx);

    gemm_tf32_kernel<<<gg, 256>>>(pctx, Wo, bo, out);
}

// round 9
// speedup vs baseline: 5.6374x; 3.7111x over previous
#include <cuda_runtime.h>
#include <cuda_fp16.h>

#define CB 4
#define CS 2048
#define CD 1024
#define CH 16
#define MTOK (CB*CS)

#define GM MTOK
#define GN CD
#define GK CD

/* half scratch (device globals: allocation-free, graph-capturable) */
__device__ __half g_hQ [MTOK * CD];
__device__ __half g_hKV[MTOK * CD];
__device__ __half g_hWq[CD * CD];
__device__ __half g_hWk[CD * CD];
__device__ __half g_hWv[CD * CD];
__device__ __half g_hWo[CD * CD];
__device__ __half g_hq [MTOK * CD];
__device__ __half g_hk [MTOK * CD];
__device__ __half g_hv [MTOK * CD];
__device__ __half g_hctx[MTOK * CD];

/* ---------------- helpers ---------------- */
__device__ __forceinline__ unsigned sptr(const void* p) {
    return (unsigned)__cvta_generic_to_shared(p);
}
__device__ __forceinline__ void ldsm4(unsigned& r0, unsigned& r1, unsigned& r2,
                                      unsigned& r3, unsigned addr) {
    asm volatile("ldmatrix.sync.aligned.m8n8.x4.shared.b16 {%0,%1,%2,%3}, [%4];"
                 : "=r"(r0), "=r"(r1), "=r"(r2), "=r"(r3) : "r"(addr));
}
__device__ __forceinline__ void ldsm4t(unsigned& r0, unsigned& r1, unsigned& r2,
                                       unsigned& r3, unsigned addr) {
    asm volatile("ldmatrix.sync.aligned.m8n8.x4.trans.shared.b16 {%0,%1,%2,%3}, [%4];"
                 : "=r"(r0), "=r"(r1), "=r"(r2), "=r"(r3) : "r"(addr));
}
__device__ __forceinline__ void mma16816(float* c, const unsigned* a,
                                         unsigned b0, unsigned b1) {
    asm volatile(
        "mma.sync.aligned.m16n8k16.row.col.f32.f16.f16.f32 "
        "{%0,%1,%2,%3}, {%4,%5,%6,%7}, {%8,%9}, {%0,%1,%2,%3};"
        : "+f"(c[0]), "+f"(c[1]), "+f"(c[2]), "+f"(c[3])
        : "r"(a[0]), "r"(a[1]), "r"(a[2]), "r"(a[3]), "r"(b0), "r"(b1));
}
__device__ __forceinline__ void cpa16(unsigned dst, const void* src) {
    asm volatile("cp.async.cg.shared.global [%0], [%1], 16;" :: "r"(dst), "l"(src));
}
__device__ __forceinline__ float ex2(float x) {
    float y; asm("ex2.approx.ftz.f32 %0, %1;" : "=f"(y) : "f"(x)); return y;
}
__device__ __forceinline__ unsigned packh2(float lo, float hi) {
    __half2 h = __float22half2_rn(make_float2(lo, hi));
    return *reinterpret_cast<unsigned*>(&h);
}

/* ---------------- fp32 -> fp16 convert ---------------- */
__global__ void f2h_kernel(const float4* __restrict__ x, uint2* __restrict__ y, int n4)
{
    int i = blockIdx.x * blockDim.x + threadIdx.x;
    if (i < n4) {
        float4 f = x[i];
        uint2 u;
        u.x = packh2(f.x, f.y);
        u.y = packh2(f.z, f.w);
        y[i] = u;
    }
}

/* ------------------------------------------------------------------ */
/* fp16 tensor-core GEMM: C[M,N] = A[M,K] @ B[K,N] + bias             */
/* 128x128x32 tile, 8 warps (warp 32x64), mma.m16n8k16, cp.async x3   */
/* ------------------------------------------------------------------ */
#define GAH 40    /* As stride (halfs): 80B;  5r%8  distinct quads    */
#define GBH 136   /* Bs stride (halfs): 272B; 17r%8 distinct quads    */
#define GEMM_SMEM ((3*128*GAH + 3*32*GBH) * 2)   /* 56832 bytes */

template<bool HALF_OUT>
__global__ __launch_bounds__(256)
void gemm_h_kernel(const __half* __restrict__ A, const __half* __restrict__ B,
                   const float* __restrict__ bias,
                   float* __restrict__ Cf, __half* __restrict__ Ch)
{
    extern __shared__ __half gsm[];
    __half* AsBase = gsm;                    /* [3][128*GAH] */
    __half* BsBase = gsm + 3 * 128 * GAH;    /* [3][32*GBH]  */

    const int tid  = threadIdx.x;
    const int lane = tid & 31;
    const int gr   = lane >> 2;
    const int tg   = lane & 3;
    const int warp = tid >> 5;
    const int wm   = (warp & 3) * 32;
    const int wn   = (warp >> 2) * 64;
    const int bm   = blockIdx.y * 128;
    const int bn   = blockIdx.x * 128;

    /* cp.async copy indices */
    const int arow = tid >> 1;            /* 0..127 */
    const int acol = (tid & 1) * 16;      /* halfs  */
    const int brow = tid >> 3;            /* 0..31  */
    const int bcol = (tid & 7) * 16;      /* halfs, 0..112 */

    const __half* Ag = A + (size_t)(bm + arow) * GK + acol;
    const __half* Bg = B + (size_t)brow * GN + bn + bcol;

    float acc[2][8][4];
#pragma unroll
    for (int mt = 0; mt < 2; mt++)
#pragma unroll
        for (int nt = 0; nt < 8; nt++)
#pragma unroll
            for (int i = 0; i < 4; i++) acc[mt][nt][i] = 0.f;

    const int l15 = lane & 15;
    const int lk8 = (lane & 16) >> 1;     /* 0 or 8 */

#define G_ISSUE(st, k0) do {                                              \
        unsigned da = sptr(AsBase + (st) * 128 * GAH + arow * GAH + acol);\
        cpa16(da,      Ag + (k0));                                        \
        cpa16(da + 16, Ag + (k0) + 8);                                    \
        unsigned db = sptr(BsBase + (st) * 32 * GBH + brow * GBH + bcol); \
        cpa16(db,      Bg + (size_t)(k0) * GN);                           \
        cpa16(db + 16, Bg + (size_t)(k0) * GN + 8);                       \
        asm volatile("cp.async.commit_group;");                           \
    } while (0)

    G_ISSUE(0, 0);
    G_ISSUE(1, 32);

    int st = 0;
    for (int kt = 0; kt < 32; kt++) {
        if (kt < 31) asm volatile("cp.async.wait_group 1;");
        else         asm volatile("cp.async.wait_group 0;");
        __syncthreads();
        if (kt < 30) { int ns = kt + 2 - ((kt + 2) / 3) * 3; G_ISSUE(ns, (kt + 2) * 32); }

        const __half* as = AsBase + st * 128 * GAH;
        const __half* bs = BsBase + st * 32 * GBH;
#pragma unroll
        for (int ks = 0; ks < 32; ks += 16) {
            unsigned af[2][4];
            ldsm4(af[0][0], af[0][1], af[0][2], af[0][3],
                  sptr(&as[(wm + l15) * GAH + ks + lk8]));
            ldsm4(af[1][0], af[1][1], af[1][2], af[1][3],
                  sptr(&as[(wm + 16 + l15) * GAH + ks + lk8]));
#pragma unroll
            for (int nt2 = 0; nt2 < 4; nt2++) {
                unsigned b0, b1, b2, b3;
                ldsm4t(b0, b1, b2, b3,
                       sptr(&bs[(ks + (lane & 7) + (lane & 8)) * GBH
                                + wn + nt2 * 16 + lk8]));
                mma16816(acc[0][2 * nt2],     af[0], b0, b1);
                mma16816(acc[1][2 * nt2],     af[1], b0, b1);
                mma16816(acc[0][2 * nt2 + 1], af[0], b2, b3);
                mma16816(acc[1][2 * nt2 + 1], af[1], b2, b3);
            }
        }
        st++; if (st == 3) st = 0;
    }
#undef G_ISSUE

    /* epilogue: bias + store */
#pragma unroll
    for (int mt = 0; mt < 2; mt++) {
#pragma unroll
        for (int nt = 0; nt < 8; nt++) {
            int row = bm + wm + mt * 16 + gr;
            int col = bn + wn + nt * 8 + tg * 2;
            float2 bb = *(const float2*)(bias + col);
            float c0 = acc[mt][nt][0] + bb.x, c1 = acc[mt][nt][1] + bb.y;
            float c2 = acc[mt][nt][2] + bb.x, c3 = acc[mt][nt][3] + bb.y;
            if (HALF_OUT) {
                *reinterpret_cast<unsigned*>(Ch + (size_t)row * GN + col) = packh2(c0, c1);
                *reinterpret_cast<unsigned*>(Ch + (size_t)(row + 8) * GN + col) = packh2(c2, c3);
            } else {
                *(float2*)(Cf + (size_t)row * GN + col) = make_float2(c0, c1);
                *(float2*)(Cf + (size_t)(row + 8) * GN + col) = make_float2(c2, c3);
            }
        }
    }
}

/* ------------------------------------------------------------------ */
/* FA2-style fp16 tensor-core flash attention (causal).               */
/* CTA = 128 q-rows x (b,h); warp owns 16 rows x full 64-col S.       */
/* Softmax fully in registers; S->P fragment conversion is register.  */
/* ------------------------------------------------------------------ */
#define FQH 72   /* smem stride (halfs): 144B; 9r%8 distinct quads */

__global__ __launch_bounds__(256, 2)
void flash_h_kernel(const __half* __restrict__ q, const __half* __restrict__ k,
                    const __half* __restrict__ v, __half* __restrict__ ctx)
{
    __shared__ __half Qs[128 * FQH];
    __shared__ __half Ks[64 * FQH];
    __shared__ __half Vs[64 * FQH];

    const int tid  = threadIdx.x;
    const int lane = tid & 31;
    const int gr   = lane >> 2;
    const int tg   = lane & 3;
    const int warp = tid >> 5;
    const int l15  = lane & 15;
    const int lk8  = (lane & 16) >> 1;   /* 0 or 8 */

    const int qt = 15 - blockIdx.x;      /* heavy tiles first */
    const int bh = blockIdx.y;
    const int b  = bh >> 4;
    const int h  = bh & 15;
    const int qbase = qt * 128;

    const __half* qp = q + ((size_t)b * CS + qbase) * CD + h * 64;
    const __half* kp = k + ((size_t)b * CS) * CD + h * 64;
    const __half* vp = v + ((size_t)b * CS) * CD + h * 64;

    /* stage Q tile (half, row-major 64 cols) */
    {
        int r  = tid >> 1;
        int c0 = (tid & 1) * 32;
        const __half* src = qp + (size_t)r * CD + c0;
#pragma unroll
        for (int j = 0; j < 4; j++)
            *(uint4*)&Qs[r * FQH + c0 + j * 8] = *(const uint4*)(src + j * 8);
    }
    __syncthreads();

    /* preload Q A-fragments (persist across all k-tiles) */
    unsigned qf[4][4];
#pragma unroll
    for (int ks = 0; ks < 4; ks++)
        ldsm4(qf[ks][0], qf[ks][1], qf[ks][2], qf[ks][3],
              sptr(&Qs[(warp * 16 + l15) * FQH + ks * 16 + lk8]));

    float o[8][4];
#pragma unroll
    for (int dt = 0; dt < 8; dt++)
#pragma unroll
        for (int i = 0; i < 4; i++) o[dt][i] = 0.f;
    float mrow0 = -1e30f, mrow1 = -1e30f;
    float lrow0 = 0.f,    lrow1 = 0.f;

    const int qrow0 = qbase + warp * 16;
    const int nkt = (qbase >> 6) + 2;
    const float SC = 0.18033688f;   /* (1/8) * log2(e) */

    for (int kt = 0; kt < nkt; kt++) {
        __syncthreads();   /* all warps done reading prev K/V */
        {
            int r  = tid >> 2;
            int c0 = (tid & 3) * 16;
            const __half* ksrc = kp + (size_t)(kt * 64 + r) * CD + c0;
            *(uint4*)&Ks[r * FQH + c0]     = *(const uint4*)(ksrc);
            *(uint4*)&Ks[r * FQH + c0 + 8] = *(const uint4*)(ksrc + 8);
            const __half* vsrc = vp + (size_t)(kt * 64 + r) * CD + c0;
            *(uint4*)&Vs[r * FQH + c0]     = *(const uint4*)(vsrc);
            *(uint4*)&Vs[r * FQH + c0 + 8] = *(const uint4*)(vsrc + 8);
        }
        __syncthreads();

        if (kt * 64 > qrow0 + 15) continue;   /* warp fully masked */

        /* S = Q @ K^T : K as B-operand via NON-trans ldmatrix */
        float s[8][4];
#pragma unroll
        for (int nt = 0; nt < 8; nt++)
#pragma unroll
            for (int i = 0; i < 4; i++) s[nt][i] = 0.f;
#pragma unroll
        for (int ks = 0; ks < 4; ks++) {
#pragma unroll
            for (int nt2 = 0; nt2 < 4; nt2++) {
                unsigned b0, b1, b2, b3;
                ldsm4(b0, b1, b2, b3,
                      sptr(&Ks[(nt2 * 16 + (lane & 7) + lk8) * FQH
                               + ks * 16 + (lane & 8)]));
                mma16816(s[2 * nt2],     qf[ks], b0, b1);
                mma16816(s[2 * nt2 + 1], qf[ks], b2, b3);
            }
        }

        /* scale into base-2 domain + causal mask */
        const bool dg = (kt * 64 + 63 > qrow0);
        const int r0r = qrow0 + gr, r1r = qrow0 + gr + 8;
#pragma unroll
        for (int nt = 0; nt < 8; nt++) {
            int col = kt * 64 + nt * 8 + 2 * tg;
            if (dg) {
                s[nt][0] = (col     > r0r) ? -1e30f : s[nt][0] * SC;
                s[nt][1] = (col + 1 > r0r) ? -1e30f : s[nt][1] * SC;
                s[nt][2] = (col     > r1r) ? -1e30f : s[nt][2] * SC;
                s[nt][3] = (col + 1 > r1r) ? -1e30f : s[nt][3] * SC;
            } else {
                s[nt][0] *= SC; s[nt][1] *= SC; s[nt][2] *= SC; s[nt][3] *= SC;
            }
        }

        /* register-only online softmax (base-2) */
        float mx0 = -1e30f, mx1 = -1e30f;
#pragma unroll
        for (int nt = 0; nt < 8; nt++) {
            mx0 = fmaxf(mx0, fmaxf(s[nt][0], s[nt][1]));
            mx1 = fmaxf(mx1, fmaxf(s[nt][2], s[nt][3]));
        }
        mx0 = fmaxf(mx0, __shfl_xor_sync(0xffffffffu, mx0, 1));
        mx0 = fmaxf(mx0, __shfl_xor_sync(0xffffffffu, mx0, 2));
        mx1 = fmaxf(mx1, __shfl_xor_sync(0xffffffffu, mx1, 1));
        mx1 = fmaxf(mx1, __shfl_xor_sync(0xffffffffu, mx1, 2));
        float mn0 = fmaxf(mrow0, mx0), mn1 = fmaxf(mrow1, mx1);
        float rs0 = ex2(mrow0 - mn0), rs1 = ex2(mrow1 - mn1);
        mrow0 = mn0; mrow1 = mn1;
        float ls0 = 0.f, ls1 = 0.f;
#pragma unroll
        for (int nt = 0; nt < 8; nt++) {
            s[nt][0] = ex2(s[nt][0] - mn0); ls0 += s[nt][0];
            s[nt][1] = ex2(s[nt][1] - mn0); ls0 += s[nt][1];
            s[nt][2] = ex2(s[nt][2] - mn1); ls1 += s[nt][2];
            s[nt][3] = ex2(s[nt][3] - mn1); ls1 += s[nt][3];
        }
        ls0 += __shfl_xor_sync(0xffffffffu, ls0, 1);
        ls0 += __shfl_xor_sync(0xffffffffu, ls0, 2);
        ls1 += __shfl_xor_sync(0xffffffffu, ls1, 1);
        ls1 += __shfl_xor_sync(0xffffffffu, ls1, 2);
        lrow0 = lrow0 * rs0 + ls0;
        lrow1 = lrow1 * rs1 + ls1;

        /* rescale O */
#pragma unroll
        for (int dt = 0; dt < 8; dt++) {
            o[dt][0] *= rs0; o[dt][1] *= rs0;
            o[dt][2] *= rs1; o[dt][3] *= rs1;
        }

        /* S(C-fragment) -> P(A-fragment): pure register packing */
        unsigned pf[4][4];
#pragma unroll
        for (int ks = 0; ks < 4; ks++) {
            pf[ks][0] = packh2(s[2 * ks][0],     s[2 * ks][1]);
            pf[ks][1] = packh2(s[2 * ks][2],     s[2 * ks][3]);
            pf[ks][2] = packh2(s[2 * ks + 1][0], s[2 * ks + 1][1]);
            pf[ks][3] = packh2(s[2 * ks + 1][2], s[2 * ks + 1][3]);
        }

        /* O += P @ V : V as B-operand via trans ldmatrix */
#pragma unroll
        for (int ks = 0; ks < 4; ks++) {
#pragma unroll
            for (int dt2 = 0; dt2 < 4; dt2++) {
                unsigned b0, b1, b2, b3;
                ldsm4t(b0, b1, b2, b3,
                       sptr(&Vs[(ks * 16 + (lane & 7) + (lane & 8)) * FQH
                                + dt2 * 16 + lk8]));
                mma16816(o[2 * dt2],     pf[ks], b0, b1);
                mma16816(o[2 * dt2 + 1], pf[ks], b2, b3);
            }
        }
    }

    /* epilogue: normalize, write half ctx */
    float inv0 = 1.f / lrow0, inv1 = 1.f / lrow1;
    __half* op = ctx + ((size_t)b * CS + qrow0) * CD + h * 64;
#pragma unroll
    for (int dt = 0; dt < 8; dt++) {
        int col = dt * 8 + 2 * tg;
        *reinterpret_cast<unsigned*>(op + (size_t)gr * CD + col) =
            packh2(o[dt][0] * inv0, o[dt][1] * inv0);
        *reinterpret_cast<unsigned*>(op + (size_t)(gr + 8) * CD + col) =
            packh2(o[dt][2] * inv1, o[dt][3] * inv1);
    }
}

/* ------------------------------------------------------------------ */
extern "C" void kernel_launch(void* const* d_in, const int* in_sizes, int n_in,
                              void* d_out, int out_size)
{
    const float* Q  = (const float*)d_in[0];
    const float* KV = (const float*)d_in[1];
    /* d_in[2] = mask — causal, applied analytically */
    const float* Wq = (const float*)d_in[3];
    const float* bq = (const float*)d_in[4];
    const float* Wk = (const float*)d_in[5];
    const float* bk = (const float*)d_in[6];
    const float* Wv = (const float*)d_in[7];
    const float* bv = (const float*)d_in[8];
    const float* Wo = (const float*)d_in[9];
    const float* bo = (const float*)d_in[10];
    float* out = (float*)d_out;

    __half *hQ, *hKV, *hWq, *hWk, *hWv, *hWo, *hq, *hk, *hv, *hctx;
    cudaGetSymbolAddress((void**)&hQ,   g_hQ);
    cudaGetSymbolAddress((void**)&hKV,  g_hKV);
    cudaGetSymbolAddress((void**)&hWq,  g_hWq);
    cudaGetSymbolAddress((void**)&hWk,  g_hWk);
    cudaGetSymbolAddress((void**)&hWv,  g_hWv);
    cudaGetSymbolAddress((void**)&hWo,  g_hWo);
    cudaGetSymbolAddress((void**)&hq,   g_hq);
    cudaGetSymbolAddress((void**)&hk,   g_hk);
    cudaGetSymbolAddress((void**)&hv,   g_hv);
    cudaGetSymbolAddress((void**)&hctx, g_hctx);

    static bool attr_done = false;
    if (!attr_done) {
        cudaFuncSetAttribute(gemm_h_kernel<true>,
                             cudaFuncAttributeMaxDynamicSharedMemorySize, GEMM_SMEM);
        cudaFuncSetAttribute(gemm_h_kernel<false>,
                             cudaFuncAttributeMaxDynamicSharedMemorySize, GEMM_SMEM);
        attr_done = true;
    }

    const int NTOK4 = MTOK * CD / 4;
    const int NW4   = CD * CD / 4;
    f2h_kernel<<<NTOK4 / 256, 256>>>((const float4*)Q,  (uint2*)hQ,  NTOK4);
    f2h_kernel<<<NTOK4 / 256, 256>>>((const float4*)KV, (uint2*)hKV, NTOK4);
    f2h_kernel<<<NW4 / 256, 256>>>((const float4*)Wq, (uint2*)hWq, NW4);
    f2h_kernel<<<NW4 / 256, 256>>>((const float4*)Wk, (uint2*)hWk, NW4);
    f2h_kernel<<<NW4 / 256, 256>>>((const float4*)Wv, (uint2*)hWv, NW4);
    f2h_kernel<<<NW4 / 256, 256>>>((const float4*)Wo, (uint2*)hWo, NW4);

    dim3 gg(GN / 128, GM / 128);   /* (8, 64) */
    gemm_h_kernel<true><<<gg, 256, GEMM_SMEM>>>(hQ,  hWq, bq, nullptr, hq);
    gemm_h_kernel<true><<<gg, 256, GEMM_SMEM>>>(hKV, hWk, bk, nullptr, hk);
    gemm_h_kernel<true><<<gg, 256, GEMM_SMEM>>>(hKV, hWv, bv, nullptr, hv);

    dim3 gf(16, CB * CH);          /* (16, 64) */
    flash_h_kernel<<<gf, 256>>>(hq, hk, hv, hctx);

    gemm_h_kernel<false><<<gg, 256, GEMM_SMEM>>>(hctx, hWo, bo, out, nullptr);
}

// round 12
// speedup vs baseline: 5.8610x; 1.0397x over previous
#include <cuda_runtime.h>
#include <cuda_fp16.h>

#define CB 4
#define CS 2048
#define CD 1024
#define CH 16
#define MTOK (CB*CS)

#define GM MTOK
#define GN CD
#define GK CD

/* half scratch (device globals: allocation-free, graph-capturable) */
__device__ __half g_hQ [MTOK * CD];
__device__ __half g_hKV[MTOK * CD];
__device__ __half g_hWq[CD * CD];
__device__ __half g_hWk[CD * CD];
__device__ __half g_hWv[CD * CD];
__device__ __half g_hWo[CD * CD];
__device__ __half g_hq [MTOK * CD];
__device__ __half g_hk [MTOK * CD];
__device__ __half g_hv [MTOK * CD];
__device__ __half g_hctx[MTOK * CD];

/* ---------------- helpers ---------------- */
__device__ __forceinline__ unsigned sptr(const void* p) {
    return (unsigned)__cvta_generic_to_shared(p);
}
__device__ __forceinline__ void ldsm4(unsigned& r0, unsigned& r1, unsigned& r2,
                                      unsigned& r3, unsigned addr) {
    asm volatile("ldmatrix.sync.aligned.m8n8.x4.shared.b16 {%0,%1,%2,%3}, [%4];"
                 : "=r"(r0), "=r"(r1), "=r"(r2), "=r"(r3) : "r"(addr));
}
__device__ __forceinline__ void ldsm4t(unsigned& r0, unsigned& r1, unsigned& r2,
                                       unsigned& r3, unsigned addr) {
    asm volatile("ldmatrix.sync.aligned.m8n8.x4.trans.shared.b16 {%0,%1,%2,%3}, [%4];"
                 : "=r"(r0), "=r"(r1), "=r"(r2), "=r"(r3) : "r"(addr));
}
__device__ __forceinline__ void mma16816(float* c, const unsigned* a,
                                         unsigned b0, unsigned b1) {
    asm volatile(
        "mma.sync.aligned.m16n8k16.row.col.f32.f16.f16.f32 "
        "{%0,%1,%2,%3}, {%4,%5,%6,%7}, {%8,%9}, {%0,%1,%2,%3};"
        : "+f"(c[0]), "+f"(c[1]), "+f"(c[2]), "+f"(c[3])
        : "r"(a[0]), "r"(a[1]), "r"(a[2]), "r"(a[3]), "r"(b0), "r"(b1));
}
__device__ __forceinline__ void cpa16(unsigned dst, const void* src) {
    asm volatile("cp.async.cg.shared.global [%0], [%1], 16;" :: "r"(dst), "l"(src));
}
__device__ __forceinline__ float ex2(float x) {
    float y; asm("ex2.approx.ftz.f32 %0, %1;" : "=f"(y) : "f"(x)); return y;
}
__device__ __forceinline__ unsigned packh2(float lo, float hi) {
    __half2 h = __float22half2_rn(make_float2(lo, hi));
    return *reinterpret_cast<unsigned*>(&h);
}

/* ---------------- fp32 -> fp16 converts (grid-stride, ILP) -------- */
__global__ void f2h_kernel(const float4* __restrict__ x, uint2* __restrict__ y, int n4)
{
    int stride = gridDim.x * blockDim.x;
    for (int i = blockIdx.x * blockDim.x + threadIdx.x; i < n4; i += stride) {
        float4 f = x[i];
        uint2 u;
        u.x = packh2(f.x, f.y);
        u.y = packh2(f.z, f.w);
        y[i] = u;
    }
}

__global__ void f2h4_kernel(const float4* __restrict__ x0, const float4* __restrict__ x1,
                            const float4* __restrict__ x2, const float4* __restrict__ x3,
                            uint2* __restrict__ y0, uint2* __restrict__ y1,
                            uint2* __restrict__ y2, uint2* __restrict__ y3, int n4)
{
    const float4* x = (blockIdx.y == 0) ? x0 : (blockIdx.y == 1) ? x1
                    : (blockIdx.y == 2) ? x2 : x3;
    uint2* y = (blockIdx.y == 0) ? y0 : (blockIdx.y == 1) ? y1
             : (blockIdx.y == 2) ? y2 : y3;
    int stride = gridDim.x * blockDim.x;
    for (int i = blockIdx.x * blockDim.x + threadIdx.x; i < n4; i += stride) {
        float4 f = x[i];
        uint2 u;
        u.x = packh2(f.x, f.y);
        u.y = packh2(f.z, f.w);
        y[i] = u;
    }
}

/* ------------------------------------------------------------------ */
/* fp16 tensor-core GEMM: C[M,N] = A[M,K] @ B[K,N] + bias             */
/* 128x128x32 tile, 8 warps (warp 32x64), mma.m16n8k16, cp.async x3   */
/* ------------------------------------------------------------------ */
#define GAH 40    /* As stride (halfs): 80B;  5r%8  distinct quads    */
#define GBH 136   /* Bs stride (halfs): 272B; 17r%8 distinct quads    */
#define GEMM_SMEM ((3*128*GAH + 3*32*GBH) * 2)   /* 56832 bytes */

template<bool HALF_OUT>
__global__ __launch_bounds__(256)
void gemm_h_kernel(const __half* __restrict__ A, const __half* __restrict__ B,
                   const float* __restrict__ bias,
                   float* __restrict__ Cf, __half* __restrict__ Ch)
{
    extern __shared__ __half gsm[];
    __half* AsBase = gsm;                    /* [3][128*GAH] */
    __half* BsBase = gsm + 3 * 128 * GAH;    /* [3][32*GBH]  */

    const int tid  = threadIdx.x;
    const int lane = tid & 31;
    const int gr   = lane >> 2;
    const int tg   = lane & 3;
    const int warp = tid >> 5;
    const int wm   = (warp & 3) * 32;
    const int wn   = (warp >> 2) * 64;
    const int bm   = blockIdx.y * 128;
    const int bn   = blockIdx.x * 128;

    const int arow = tid >> 1;            /* 0..127 */
    const int acol = (tid & 1) * 16;      /* halfs  */
    const int brow = tid >> 3;            /* 0..31  */
    const int bcol = (tid & 7) * 16;      /* halfs  */

    const __half* Ag = A + (size_t)(bm + arow) * GK + acol;
    const __half* Bg = B + (size_t)brow * GN + bn + bcol;

    float acc[2][8][4];
#pragma unroll
    for (int mt = 0; mt < 2; mt++)
#pragma unroll
        for (int nt = 0; nt < 8; nt++)
#pragma unroll
            for (int i = 0; i < 4; i++) acc[mt][nt][i] = 0.f;

    const int l15 = lane & 15;
    const int lk8 = (lane & 16) >> 1;     /* 0 or 8 */

#define G_ISSUE(st, k0) do {                                              \
        unsigned da = sptr(AsBase + (st) * 128 * GAH + arow * GAH + acol);\
        cpa16(da,      Ag + (k0));                                        \
        cpa16(da + 16, Ag + (k0) + 8);                                    \
        unsigned db = sptr(BsBase + (st) * 32 * GBH + brow * GBH + bcol); \
        cpa16(db,      Bg + (size_t)(k0) * GN);                           \
        cpa16(db + 16, Bg + (size_t)(k0) * GN + 8);                       \
        asm volatile("cp.async.commit_group;");                           \
    } while (0)

    G_ISSUE(0, 0);
    G_ISSUE(1, 32);

    int st = 0;
    for (int kt = 0; kt < 32; kt++) {
        if (kt < 31) asm volatile("cp.async.wait_group 1;");
        else         asm volatile("cp.async.wait_group 0;");
        __syncthreads();
        if (kt < 30) { int ns = kt + 2 - ((kt + 2) / 3) * 3; G_ISSUE(ns, (kt + 2) * 32); }

        const __half* as = AsBase + st * 128 * GAH;
        const __half* bs = BsBase + st * 32 * GBH;
#pragma unroll
        for (int ks = 0; ks < 32; ks += 16) {
            unsigned af[2][4];
            ldsm4(af[0][0], af[0][1], af[0][2], af[0][3],
                  sptr(&as[(wm + l15) * GAH + ks + lk8]));
            ldsm4(af[1][0], af[1][1], af[1][2], af[1][3],
                  sptr(&as[(wm + 16 + l15) * GAH + ks + lk8]));
#pragma unroll
            for (int nt2 = 0; nt2 < 4; nt2++) {
                unsigned b0, b1, b2, b3;
                ldsm4t(b0, b1, b2, b3,
                       sptr(&bs[(ks + (lane & 7) + (lane & 8)) * GBH
                                + wn + nt2 * 16 + lk8]));
                mma16816(acc[0][2 * nt2],     af[0], b0, b1);
                mma16816(acc[1][2 * nt2],     af[1], b0, b1);
                mma16816(acc[0][2 * nt2 + 1], af[0], b2, b3);
                mma16816(acc[1][2 * nt2 + 1], af[1], b2, b3);
            }
        }
        st++; if (st == 3) st = 0;
    }
#undef G_ISSUE

    /* epilogue: bias + store */
#pragma unroll
    for (int mt = 0; mt < 2; mt++) {
#pragma unroll
        for (int nt = 0; nt < 8; nt++) {
            int row = bm + wm + mt * 16 + gr;
            int col = bn + wn + nt * 8 + tg * 2;
            float2 bb = *(const float2*)(bias + col);
            float c0 = acc[mt][nt][0] + bb.x, c1 = acc[mt][nt][1] + bb.y;
            float c2 = acc[mt][nt][2] + bb.x, c3 = acc[mt][nt][3] + bb.y;
            if (HALF_OUT) {
                *reinterpret_cast<unsigned*>(Ch + (size_t)row * GN + col) = packh2(c0, c1);
                *reinterpret_cast<unsigned*>(Ch + (size_t)(row + 8) * GN + col) = packh2(c2, c3);
            } else {
                *(float2*)(Cf + (size_t)row * GN + col) = make_float2(c0, c1);
                *(float2*)(Cf + (size_t)(row + 8) * GN + col) = make_float2(c2, c3);
            }
        }
    }
}

/* ------------------------------------------------------------------ */
/* FA2-style fp16 tensor-core flash attention (causal).               */
/* CTA = 128 q-rows x (b,h); warp owns 16 rows x full 64-col S.       */
/* K/V double-buffered via cp.async; 1 barrier per k-tile.            */
/* ------------------------------------------------------------------ */
#define FQH 72   /* smem stride (halfs): 144B; 9r%8 distinct quads */
#define FLASH_SMEM ((128*FQH + 4*64*FQH) * 2)   /* 55296 bytes */

__global__ __launch_bounds__(256, 2)
void flash_h_kernel(const __half* __restrict__ q, const __half* __restrict__ k,
                    const __half* __restrict__ v, __half* __restrict__ ctx)
{
    extern __shared__ __half fsm[];
    __half* Qs  = fsm;                       /* [128][FQH] */
    __half* KsB = fsm + 128 * FQH;           /* [2][64][FQH] */
    __half* VsB = fsm + 128 * FQH + 2 * 64 * FQH;

    const int tid  = threadIdx.x;
    const int lane = tid & 31;
    const int gr   = lane >> 2;
    const int tg   = lane & 3;
    const int warp = tid >> 5;
    const int l15  = lane & 15;
    const int lk8  = (lane & 16) >> 1;   /* 0 or 8 */

    const int qt = 15 - blockIdx.x;      /* heavy tiles first */
    const int bh = blockIdx.y;
    const int b  = bh >> 4;
    const int h  = bh & 15;
    const int qbase = qt * 128;

    const __half* qp = q + ((size_t)b * CS + qbase) * CD + h * 64;
    const __half* kp = k + ((size_t)b * CS) * CD + h * 64;
    const __half* vp = v + ((size_t)b * CS) * CD + h * 64;

    /* cp.async staging indices for K/V (64 rows x 64 halfs each) */
    const int srow = tid >> 2;           /* 0..63 */
    const int scol = (tid & 3) * 16;     /* 0,16,32,48 */

#define F_ISSUE(kt, buf) do {                                                \
        const __half* ksrc = kp + (size_t)((kt) * 64 + srow) * CD + scol;    \
        unsigned dk = sptr(KsB + (buf) * 64 * FQH + srow * FQH + scol);      \
        cpa16(dk,      ksrc);                                                \
        cpa16(dk + 16, ksrc + 8);                                            \
        const __half* vsrc = vp + (size_t)((kt) * 64 + srow) * CD + scol;    \
        unsigned dv = sptr(VsB + (buf) * 64 * FQH + srow * FQH + scol);      \
        cpa16(dv,      vsrc);                                                \
        cpa16(dv + 16, vsrc + 8);                                            \
        asm volatile("cp.async.commit_group;");                              \
    } while (0)

    /* issue first K/V tile, then stage Q */
    F_ISSUE(0, 0);
    {
        int r  = tid >> 1;
        int c0 = (tid & 1) * 32;
        const __half* src = qp + (size_t)r * CD + c0;
#pragma unroll
        for (int j = 0; j < 4; j++)
            *(uint4*)&Qs[r * FQH + c0 + j * 8] = *(const uint4*)(src + j * 8);
    }
    __syncthreads();

    /* preload Q A-fragments (persist across all k-tiles) */
    unsigned qf[4][4];
#pragma unroll
    for (int ks = 0; ks < 4; ks++)
        ldsm4(qf[ks][0], qf[ks][1], qf[ks][2], qf[ks][3],
              sptr(&Qs[(warp * 16 + l15) * FQH + ks * 16 + lk8]));

    float o[8][4];
#pragma unroll
    for (int dt = 0; dt < 8; dt++)
#pragma unroll
        for (int i = 0; i < 4; i++) o[dt][i] = 0.f;
    float mrow0 = -1e30f, mrow1 = -1e30f;
    float lrow0 = 0.f,    lrow1 = 0.f;

    const int qrow0 = qbase + warp * 16;
    const int nkt = (qbase >> 6) + 2;
    const float SC = 0.18033688f;   /* (1/8) * log2(e) */

    int buf = 0;
    for (int kt = 0; kt < nkt; kt++) {
        asm volatile("cp.async.wait_group 0;");
        __syncthreads();   /* K/V[buf] ready; all warps done with buf^1 */
        if (kt + 1 < nkt) F_ISSUE(kt + 1, buf ^ 1);

        if (kt * 64 <= qrow0 + 15) {
            const __half* Ks = KsB + buf * 64 * FQH;
            const __half* Vs = VsB + buf * 64 * FQH;

            /* S = Q @ K^T : K as B-operand via NON-trans ldmatrix */
            float s[8][4];
#pragma unroll
            for (int nt = 0; nt < 8; nt++)
#pragma unroll
                for (int i = 0; i < 4; i++) s[nt][i] = 0.f;
#pragma unroll
            for (int ks = 0; ks < 4; ks++) {
#pragma unroll
                for (int nt2 = 0; nt2 < 4; nt2++) {
                    unsigned b0, b1, b2, b3;
                    ldsm4(b0, b1, b2, b3,
                          sptr(&Ks[(nt2 * 16 + (lane & 7) + lk8) * FQH
                                   + ks * 16 + (lane & 8)]));
                    mma16816(s[2 * nt2],     qf[ks], b0, b1);
                    mma16816(s[2 * nt2 + 1], qf[ks], b2, b3);
                }
            }

            /* scale into base-2 domain + causal mask */
            const bool dg = (kt * 64 + 63 > qrow0);
            const int r0r = qrow0 + gr, r1r = qrow0 + gr + 8;
#pragma unroll
            for (int nt = 0; nt < 8; nt++) {
                int col = kt * 64 + nt * 8 + 2 * tg;
                if (dg) {
                    s[nt][0] = (col     > r0r) ? -1e30f : s[nt][0] * SC;
                    s[nt][1] = (col + 1 > r0r) ? -1e30f : s[nt][1] * SC;
                    s[nt][2] = (col     > r1r) ? -1e30f : s[nt][2] * SC;
                    s[nt][3] = (col + 1 > r1r) ? -1e30f : s[nt][3] * SC;
                } else {
                    s[nt][0] *= SC; s[nt][1] *= SC;
                    s[nt][2] *= SC; s[nt][3] *= SC;
                }
            }

            /* register-only online softmax (base-2) */
            float mx0 = -1e30f, mx1 = -1e30f;
#pragma unroll
            for (int nt = 0; nt < 8; nt++) {
                mx0 = fmaxf(mx0, fmaxf(s[nt][0], s[nt][1]));
                mx1 = fmaxf(mx1, fmaxf(s[nt][2], s[nt][3]));
            }
            mx0 = fmaxf(mx0, __shfl_xor_sync(0xffffffffu, mx0, 1));
            mx0 = fmaxf(mx0, __shfl_xor_sync(0xffffffffu, mx0, 2));
            mx1 = fmaxf(mx1, __shfl_xor_sync(0xffffffffu, mx1, 1));
            mx1 = fmaxf(mx1, __shfl_xor_sync(0xffffffffu, mx1, 2));
            float mn0 = fmaxf(mrow0, mx0), mn1 = fmaxf(mrow1, mx1);
            float rs0 = ex2(mrow0 - mn0), rs1 = ex2(mrow1 - mn1);
            mrow0 = mn0; mrow1 = mn1;
            float ls0 = 0.f, ls1 = 0.f;
#pragma unroll
            for (int nt = 0; nt < 8; nt++) {
                s[nt][0] = ex2(s[nt][0] - mn0); ls0 += s[nt][0];
                s[nt][1] = ex2(s[nt][1] - mn0); ls0 += s[nt][1];
                s[nt][2] = ex2(s[nt][2] - mn1); ls1 += s[nt][2];
                s[nt][3] = ex2(s[nt][3] - mn1); ls1 += s[nt][3];
            }
            ls0 += __shfl_xor_sync(0xffffffffu, ls0, 1);
            ls0 += __shfl_xor_sync(0xffffffffu, ls0, 2);
            ls1 += __shfl_xor_sync(0xffffffffu, ls1, 1);
            ls1 += __shfl_xor_sync(0xffffffffu, ls1, 2);
            lrow0 = lrow0 * rs0 + ls0;
            lrow1 = lrow1 * rs1 + ls1;

            /* rescale O */
#pragma unroll
            for (int dt = 0; dt < 8; dt++) {
                o[dt][0] *= rs0; o[dt][1] *= rs0;
                o[dt][2] *= rs1; o[dt][3] *= rs1;
            }

            /* S(C-fragment) -> P(A-fragment): pure register packing */
            unsigned pf[4][4];
#pragma unroll
            for (int ks = 0; ks < 4; ks++) {
                pf[ks][0] = packh2(s[2 * ks][0],     s[2 * ks][1]);
                pf[ks][1] = packh2(s[2 * ks][2],     s[2 * ks][3]);
                pf[ks][2] = packh2(s[2 * ks + 1][0], s[2 * ks + 1][1]);
                pf[ks][3] = packh2(s[2 * ks + 1][2], s[2 * ks + 1][3]);
            }

            /* O += P @ V : V as B-operand via trans ldmatrix */
#pragma unroll
            for (int ks = 0; ks < 4; ks++) {
#pragma unroll
                for (int dt2 = 0; dt2 < 4; dt2++) {
                    unsigned b0, b1, b2, b3;
                    ldsm4t(b0, b1, b2, b3,
                           sptr(&Vs[(ks * 16 + (lane & 7) + (lane & 8)) * FQH
                                    + dt2 * 16 + lk8]));
                    mma16816(o[2 * dt2],     pf[ks], b0, b1);
                    mma16816(o[2 * dt2 + 1], pf[ks], b2, b3);
                }
            }
        }
        buf ^= 1;
    }
#undef F_ISSUE

    /* epilogue: normalize, write half ctx */
    float inv0 = 1.f / lrow0, inv1 = 1.f / lrow1;
    __half* op = ctx + ((size_t)b * CS + qrow0) * CD + h * 64;
#pragma unroll
    for (int dt = 0; dt < 8; dt++) {
        int col = dt * 8 + 2 * tg;
        *reinterpret_cast<unsigned*>(op + (size_t)gr * CD + col) =
            packh2(o[dt][0] * inv0, o[dt][1] * inv0);
        *reinterpret_cast<unsigned*>(op + (size_t)(gr + 8) * CD + col) =
            packh2(o[dt][2] * inv1, o[dt][3] * inv1);
    }
}

/* ------------------------------------------------------------------ */
extern "C" void kernel_launch(void* const* d_in, const int* in_sizes, int n_in,
                              void* d_out, int out_size)
{
    const float* Q  = (const float*)d_in[0];
    const float* KV = (const float*)d_in[1];
    /* d_in[2] = mask — causal, applied analytically */
    const float* Wq = (const float*)d_in[3];
    const float* bq = (const float*)d_in[4];
    const float* Wk = (const float*)d_in[5];
    const float* bk = (const float*)d_in[6];
    const float* Wv = (const float*)d_in[7];
    const float* bv = (const float*)d_in[8];
    const float* Wo = (const float*)d_in[9];
    const float* bo = (const float*)d_in[10];
    float* out = (float*)d_out;

    __half *hQ, *hKV, *hWq, *hWk, *hWv, *hWo, *hq, *hk, *hv, *hctx;
    cudaGetSymbolAddress((void**)&hQ,   g_hQ);
    cudaGetSymbolAddress((void**)&hKV,  g_hKV);
    cudaGetSymbolAddress((void**)&hWq,  g_hWq);
    cudaGetSymbolAddress((void**)&hWk,  g_hWk);
    cudaGetSymbolAddress((void**)&hWv,  g_hWv);
    cudaGetSymbolAddress((void**)&hWo,  g_hWo);
    cudaGetSymbolAddress((void**)&hq,   g_hq);
    cudaGetSymbolAddress((void**)&hk,   g_hk);
    cudaGetSymbolAddress((void**)&hv,   g_hv);
    cudaGetSymbolAddress((void**)&hctx, g_hctx);

    static bool attr_done = false;
    if (!attr_done) {
        cudaFuncSetAttribute(gemm_h_kernel<true>,
                             cudaFuncAttributeMaxDynamicSharedMemorySize, GEMM_SMEM);
        cudaFuncSetAttribute(gemm_h_kernel<false>,
                             cudaFuncAttributeMaxDynamicSharedMemorySize, GEMM_SMEM);
        cudaFuncSetAttribute(flash_h_kernel,
                             cudaFuncAttributeMaxDynamicSharedMemorySize, FLASH_SMEM);
        attr_done = true;
    }

    const int NTOK4 = MTOK * CD / 4;   /* 2M float4 */
    const int NW4   = CD * CD / 4;     /* 256K float4 */
    /* big converts: grid-stride, ~7 float4/thread */
    f2h_kernel<<<1184, 256>>>((const float4*)Q,  (uint2*)hQ,  NTOK4);
    f2h_kernel<<<1184, 256>>>((const float4*)KV, (uint2*)hKV, NTOK4);
    /* all four weights in one launch */
    f2h4_kernel<<<dim3(296, 4), 256>>>(
        (const float4*)Wq, (const float4*)Wk, (const float4*)Wv, (const float4*)Wo,
        (uint2*)hWq, (uint2*)hWk, (uint2*)hWv, (uint2*)hWo, NW4);

    dim3 gg(GN / 128, GM / 128);   /* (8, 64) */
    gemm_h_kernel<true><<<gg, 256, GEMM_SMEM>>>(hQ,  hWq, bq, nullptr, hq);
    gemm_h_kernel<true><<<gg, 256, GEMM_SMEM>>>(hKV, hWk, bk, nullptr, hk);
    gemm_h_kernel<true><<<gg, 256, GEMM_SMEM>>>(hKV, hWv, bv, nullptr, hv);

    dim3 gf(16, CB * CH);          /* (16, 64) */
    flash_h_kernel<<<gf, 256, FLASH_SMEM>>>(hq, hk, hv, hctx);

    gemm_h_kernel<false><<<gg, 256, GEMM_SMEM>>>(hctx, hWo, bo, out, nullptr);
}